// round 1
// baseline (speedup 1.0000x reference)
#include <cuda_runtime.h>
#include <math.h>

#define LROWS    512
#define NS       8192          // samples per row
#define NREF     8192          // reference grid points
#define NG       (3*NREF)      // 24576 circular-CDF grid points
#define NTHREADS 512
#define IPT      (NS/NTHREADS)   // 16 items per thread
#define KPT      (NREF/NTHREADS) // 16 inversion queries per thread

__device__ float g_rowsum[LROWS];

// Dynamic SMEM layout:
//   float xs[NS]       sorted samples                  32768 B
//   float cw[NS]       weights -> cdf (in place)       32768 B
//   int   offs[NS+1]   bucket offsets                  32772 B
//   float ecdf[NG]     circular CDF on grid            98304 B
// total 196612 B dynamic + ~6.2 KB static

__device__ __forceinline__ void emb_pass(
    const float* __restrict__ gx, const float* __restrict__ gw,
    float* xs, float* cw, int* offs, float* ecdf,
    float* fredA, float* fredB, int* ired, float* s_alpha_p,
    int tid, float (&h)[KPT])
{
    const float step = 3.0f / 24575.0f;

    // ---- 1. zero histogram -------------------------------------------------
    for (int i = tid; i <= NS; i += NTHREADS) offs[i] = 0;
    __syncthreads();

    // ---- 2. load rows, histogram (exact bucket map), alpha partials --------
    float lx[IPT], lw[IPT];
    float pxw = 0.f, pw = 0.f;
#pragma unroll
    for (int i = 0; i < IPT; i++) {
        int idx = tid + i * NTHREADS;           // coalesced
        float x = gx[idx];
        float w = gw[idx];
        lx[i] = x; lw[i] = w;
        pxw += x * w; pw += w;
        int b = (int)(x * 8192.0f);             // exact: *2^13, x>=0
        if (b > NS - 1) b = NS - 1;
        atomicAdd(&offs[b + 1], 1);
    }

    // alpha = weighted mean - 0.5 (deterministic tree reduction)
    fredA[tid] = pxw; fredB[tid] = pw;
    __syncthreads();                            // also fences histogram atomics
    for (int s = NTHREADS / 2; s > 0; s >>= 1) {
        if (tid < s) { fredA[tid] += fredA[tid + s]; fredB[tid] += fredB[tid + s]; }
        __syncthreads();
    }
    if (tid == 0) *s_alpha_p = fredA[0] / fredB[0] - 0.5f;

    // ---- 3. exclusive scan of counts -> bucket offsets ---------------------
    int c[IPT]; int runc = 0;
#pragma unroll
    for (int j = 0; j < IPT; j++) {
        runc += offs[1 + tid * IPT + j];
        c[j] = runc;                            // local inclusive
    }
    ired[tid] = runc;
    __syncthreads();
    for (int d = 1; d < NTHREADS; d <<= 1) {    // Hillis-Steele inclusive
        int v = (tid >= d) ? ired[tid - d] : 0;
        __syncthreads();
        ired[tid] += v;
        __syncthreads();
    }
    int exc = ired[tid] - runc;
#pragma unroll
    for (int j = 0; j < IPT; j++) offs[1 + tid * IPT + j] = exc + c[j];
    __syncthreads();

    // ---- 4. scatter (counting sort), cursors live in ecdf region -----------
    int* cursor = (int*)ecdf;
    for (int b = tid; b < NS; b += NTHREADS) cursor[b] = offs[b];
    __syncthreads();
#pragma unroll
    for (int i = 0; i < IPT; i++) {
        float x = lx[i];
        int b = (int)(x * 8192.0f);
        if (b > NS - 1) b = NS - 1;
        int pos = atomicAdd(&cursor[b], 1);
        xs[pos] = x;
        cw[pos] = lw[i];
    }
    __syncthreads();

    // ---- 5. per-bucket insertion sort (avg occupancy 1) --------------------
    for (int b = tid; b < NS; b += NTHREADS) {
        int s = offs[b], e = offs[b + 1];
        for (int i = s + 1; i < e; i++) {
            float kx = xs[i], kv = cw[i];
            int j = i - 1;
            while (j >= s && xs[j] > kx) { xs[j+1] = xs[j]; cw[j+1] = cw[j]; j--; }
            xs[j+1] = kx; cw[j+1] = kv;
        }
    }
    __syncthreads();

    // ---- 6. cumsum of sorted weights -> cdf (in place) ---------------------
    float v[IPT]; float runf = 0.f;
#pragma unroll
    for (int j = 0; j < IPT; j++) { runf += cw[tid * IPT + j]; v[j] = runf; }
    fredA[tid] = runf;
    __syncthreads();
    for (int d = 1; d < NTHREADS; d <<= 1) {
        float t = (tid >= d) ? fredA[tid - d] : 0.f;
        __syncthreads();
        fredA[tid] += t;
        __syncthreads();
    }
    float excf = fredA[tid] - runf;
#pragma unroll
    for (int j = 0; j < IPT; j++) cw[tid * IPT + j] = excf + v[j];
    __syncthreads();

    // ---- 7. rasterize circular CDF onto 3N grid ----------------------------
    // ecdf[j] = floor(xnew) + interp(xs, cdf, frac(xnew)); lower_bound via the
    // exact bucket map: all samples in buckets < b are < r, all in buckets > b
    // are > r, so only bucket b needs a strict-less scan.
    for (int j = tid; j < NG; j += NTHREADS) {
        float xn = fmaf((float)j, step, -1.0f);
        float fi = floorf(xn);
        float r = xn - fi;
        int b = (int)(r * 8192.0f);
        if (b > NS - 1) b = NS - 1;
        if (b < 0) b = 0;
        int lo = offs[b], hi = offs[b + 1];
        int cnt = lo;
        for (int i = lo; i < hi; i++) cnt += (xs[i] < r) ? 1 : 0;
        int idx = cnt - 1;
        idx = idx < 0 ? 0 : (idx > NS - 2 ? NS - 2 : idx);
        float x0 = xs[idx], x1v = xs[idx + 1];
        float y0 = cw[idx], y1 = cw[idx + 1];
        float t = (r - x0) / (x1v - x0);
        ecdf[j] = fi + fmaf(t, y1 - y0, y0);
    }
    __syncthreads();

    float alpha = *s_alpha_p;

    // ---- 8. invert: h(x_k) = interp(ecdf, xnew, x_k - alpha) - x_k ---------
#pragma unroll
    for (int j = 0; j < KPT; j++) {
        int k = tid + j * NTHREADS;
        float xk = (float)k * (1.0f / 8192.0f);
        float y = xk - alpha;
        int lo = 0, hi = NG;                    // lower_bound binary search
        while (lo < hi) {
            int mid = (lo + hi) >> 1;
            if (ecdf[mid] < y) lo = mid + 1; else hi = mid;
        }
        int idx = lo - 1;
        idx = idx < 0 ? 0 : (idx > NG - 2 ? NG - 2 : idx);
        float e0 = ecdf[idx], e1 = ecdf[idx + 1];
        float xn0 = fmaf((float)idx, step, -1.0f);
        float xn1 = fmaf((float)(idx + 1), step, -1.0f);
        float t = (y - e0) / (e1 - e0);
        h[j] = fmaf(t, xn1 - xn0, xn0) - xk;
    }
    __syncthreads();   // shared arrays reused by next pass
}

__global__ void __launch_bounds__(NTHREADS, 1)
lcot_row_kernel(const float* __restrict__ x1, const float* __restrict__ w1,
                const float* __restrict__ x2, const float* __restrict__ w2)
{
    extern __shared__ char smem_raw[];
    float* xs   = (float*)smem_raw;
    float* cw   = xs + NS;
    int*   offs = (int*)(cw + NS);
    float* ecdf = (float*)(offs + (NS + 1));

    __shared__ float fredA[NTHREADS];
    __shared__ float fredB[NTHREADS];
    __shared__ int   ired[NTHREADS];
    __shared__ float s_alpha;

    const int tid = threadIdx.x;
    const int row = blockIdx.x;
    const size_t base = (size_t)row * NS;

    float h1[KPT], h2[KPT];
    emb_pass(x1 + base, w1 + base, xs, cw, offs, ecdf,
             fredA, fredB, ired, &s_alpha, tid, h1);
    emb_pass(x2 + base, w2 + base, xs, cw, offs, ecdf,
             fredA, fredB, ired, &s_alpha, tid, h2);

    // circular distance accumulation
    float acc = 0.f;
#pragma unroll
    for (int j = 0; j < KPT; j++) {
        float d = fabsf(h2[j] - h1[j]);
        float m = fminf(d, 1.0f - d);
        acc += m * m;
    }
    fredA[tid] = acc;
    __syncthreads();
    for (int s = NTHREADS / 2; s > 0; s >>= 1) {
        if (tid < s) fredA[tid] += fredA[tid + s];
        __syncthreads();
    }
    if (tid == 0) g_rowsum[row] = fredA[0];
}

__global__ void lcot_finalize_kernel(float* __restrict__ out)
{
    __shared__ float r[LROWS];
    int t = threadIdx.x;
    r[t] = g_rowsum[t];
    __syncthreads();
    for (int s = LROWS / 2; s > 0; s >>= 1) {
        if (t < s) r[t] += r[t + s];
        __syncthreads();
    }
    if (t == 0) out[0] = sqrtf(r[0] / (float)LROWS);
}

extern "C" void kernel_launch(void* const* d_in, const int* in_sizes, int n_in,
                              void* d_out, int out_size)
{
    const float* x1 = (const float*)d_in[0];
    const float* w1 = (const float*)d_in[1];
    const float* x2 = (const float*)d_in[2];
    const float* w2 = (const float*)d_in[3];
    float* out = (float*)d_out;

    size_t dyn = (size_t)(2 * NS) * sizeof(float)
               + (size_t)(NS + 1) * sizeof(int)
               + (size_t)NG * sizeof(float);   // 196612 B

    cudaFuncSetAttribute(lcot_row_kernel,
                         cudaFuncAttributeMaxDynamicSharedMemorySize, (int)dyn);

    lcot_row_kernel<<<LROWS, NTHREADS, dyn>>>(x1, w1, x2, w2);
    lcot_finalize_kernel<<<1, LROWS>>>(out);
}